// round 3
// baseline (speedup 1.0000x reference)
#include <cuda_runtime.h>
#include <math.h>

#define B_   2
#define C_   256
#define HW   65536
#define TABN 2048

// ---- scratch (static __device__ arrays: allocation-free per harness rules) ----
__device__ float g_P[(size_t)B_ * HW * 768];      // per-source-pixel projections [b*HW][Qf|Kf|Vf]
__device__ float g_Wall[768 * 256];               // packed [Wq;Wk;Wv] row-major [j][c]
__device__ float g_kpe[4 * 256];                  // bk + pe_warp[uv]·Wk^T
__device__ float g_vpe[4 * 256];                  // bv + pe_warp[uv]·Wv^T
__device__ float g_qpeY[(TABN + 1) * 256];        // (pe_y(t)·Wq^T) lerp table
__device__ float g_qpeX[(TABN + 1) * 256];        // (pe_x(t)·Wq^T) lerp table

// ======================= prep kernels =======================

__global__ void pack_wall_kernel(const float* __restrict__ Wq,
                                 const float* __restrict__ Wk,
                                 const float* __restrict__ Wv) {
    int j = blockIdx.x;           // 0..767
    int c = threadIdx.x;          // 0..255
    const float* W = (j < 256) ? Wq : ((j < 512) ? Wk : Wv);
    g_Wall[j * 256 + c] = W[(j & 255) * 256 + c];
}

// pos_bias: sine PE of window coords (u,v) with card=(U-1,V-1)=(1,1); fold with bk/bv.
__global__ void build_kvpe_kernel(const float* __restrict__ Wk, const float* __restrict__ bk,
                                  const float* __restrict__ Wv, const float* __restrict__ bv) {
    int uv = blockIdx.x;          // 0..3 : (u = uv>>1 -> y, v = uv&1 -> x)
    int j  = threadIdx.x;         // 0..255
    __shared__ float pe[256];
    {
        int half = j >> 7;        // 0: y-half, 1: x-half
        int cc = j & 127;
        int m = cc >> 1;
        float coord = half ? (float)(uv & 1) : (float)(uv >> 1);
        float base = coord / (1.0f + 1e-6f) * 6.2831853071795864769f;
        float arg  = base * powf(10000.0f, -(float)(2 * m) / 128.0f);
        pe[j] = (cc & 1) ? cosf(arg) : sinf(arg);
    }
    __syncthreads();
    float sk = bk[j], sv = bv[j];
    const float* wkr = Wk + j * 256;
    const float* wvr = Wv + j * 256;
    #pragma unroll 4
    for (int c = 0; c < 256; c++) {
        float p = pe[c];
        sk = fmaf(p, wkr[c], sk);
        sv = fmaf(p, wvr[c], sv);
    }
    g_kpe[uv * 256 + j] = sk;
    g_vpe[uv * 256 + j] = sv;
}

// qpe tables: pe_curr uses card=(U,V)=(2,2) on the fractional offset t in [0,1].
// Table g in [0,TABN]; both halves use the identical pe(t) function, only Wq columns differ.
__global__ void build_qpetab_kernel(const float* __restrict__ Wq) {
    int g = blockIdx.x;           // 0..TABN
    int j = threadIdx.x;          // 0..255
    __shared__ float pe[128];
    if (j < 128) {
        int m = j >> 1;
        float t = (float)g / (float)TABN;
        float base = t / (2.0f + 1e-6f) * 6.2831853071795864769f;
        float arg  = base * powf(10000.0f, -(float)(2 * m) / 128.0f);
        pe[j] = (j & 1) ? cosf(arg) : sinf(arg);
    }
    __syncthreads();
    const float* wr = Wq + j * 256;
    float sy = 0.f, sx = 0.f;
    #pragma unroll 4
    for (int c = 0; c < 128; c++) {
        float p = pe[c];
        sy = fmaf(p, wr[c], sy);
        sx = fmaf(p, wr[128 + c], sx);
    }
    g_qpeY[g * 256 + j] = sy;
    g_qpeX[g * 256 + j] = sx;
}

// ======================= projection GEMM =======================
// P[b*HW + p][j] = sum_c feat[b][c][p] * Wall[j][c],  M=65536/batch, N=768, K=256.
// A is [C][HW] (p contiguous -> coalesced), B is Wall row-major.
#define GBM 128
#define GBN 128
#define GBK 8

__global__ void __launch_bounds__(256, 2) proj_gemm_kernel(const float* __restrict__ feat) {
    __shared__ float As[GBK][GBM];
    __shared__ float Bs[GBK][GBN];

    int b  = blockIdx.z;
    int m0 = blockIdx.y * GBM;
    int n0 = blockIdx.x * GBN;
    int tid = threadIdx.x;
    int tr = tid >> 4;            // 0..15
    int tc = tid & 15;            // 0..15

    float acc[8][8];
    #pragma unroll
    for (int i = 0; i < 8; i++)
        #pragma unroll
        for (int j = 0; j < 8; j++) acc[i][j] = 0.f;

    int la_r = tid >> 5;                 // 0..7  (c within k-tile)
    int la_c = (tid & 31) << 2;          // 0..124 (p)
    int lb_j = tid >> 1;                 // 0..127
    int lb_c = (tid & 1) << 2;           // 0 or 4

    const float* Aptr = feat + (size_t)b * C_ * HW + (size_t)la_r * HW + m0 + la_c;
    const float* Bptr = g_Wall + (size_t)(n0 + lb_j) * 256 + lb_c;

    for (int k0 = 0; k0 < 256; k0 += GBK) {
        float4 av = *(const float4*)(Aptr + (size_t)k0 * HW);
        *(float4*)&As[la_r][la_c] = av;
        float4 bv = *(const float4*)(Bptr + k0);
        Bs[lb_c + 0][lb_j] = bv.x;
        Bs[lb_c + 1][lb_j] = bv.y;
        Bs[lb_c + 2][lb_j] = bv.z;
        Bs[lb_c + 3][lb_j] = bv.w;
        __syncthreads();
        #pragma unroll
        for (int kk = 0; kk < GBK; kk++) {
            float a[8], bb[8];
            *(float4*)&a[0]  = *(const float4*)&As[kk][tr * 4];
            *(float4*)&a[4]  = *(const float4*)&As[kk][64 + tr * 4];
            *(float4*)&bb[0] = *(const float4*)&Bs[kk][tc * 4];
            *(float4*)&bb[4] = *(const float4*)&Bs[kk][64 + tc * 4];
            #pragma unroll
            for (int i = 0; i < 8; i++)
                #pragma unroll
                for (int j = 0; j < 8; j++)
                    acc[i][j] = fmaf(a[i], bb[j], acc[i][j]);
        }
        __syncthreads();
    }

    #pragma unroll
    for (int i = 0; i < 8; i++) {
        int mm = m0 + ((i < 4) ? (tr * 4 + i) : (64 + tr * 4 + (i - 4)));
        float* op = g_P + (size_t)(b * HW + mm) * 768 + n0;
        float4 v0 = make_float4(acc[i][0], acc[i][1], acc[i][2], acc[i][3]);
        float4 v1 = make_float4(acc[i][4], acc[i][5], acc[i][6], acc[i][7]);
        *(float4*)(op + tc * 4)      = v0;
        *(float4*)(op + 64 + tc * 4) = v1;
    }
}

// ======================= attention epilogue =======================
// 1 query vs 4 keys per target pixel. Warp: lane l owns channels [8l, 8l+8);
// head h = l/4 (lanes 4h..4h+3 cover its 32 dims -> 2-shfl logit reduction).

__device__ __forceinline__ void ld8(float* r, const float* p) {
    float4 v0 = *(const float4*)p;
    float4 v1 = *(const float4*)(p + 4);
    r[0] = v0.x; r[1] = v0.y; r[2] = v0.z; r[3] = v0.w;
    r[4] = v1.x; r[5] = v1.y; r[6] = v1.z; r[7] = v1.w;
}

__global__ void __launch_bounds__(128) attn_epilogue_kernel(
    const float* __restrict__ offset, const float* __restrict__ bq,
    float* __restrict__ out) {
    __shared__ float s_kpe[4][256];
    __shared__ float s_vpe[4][256];
    __shared__ float s_out[256 * 33];    // [channel][px], pitch 33 to dodge worst conflicts

    int tid = threadIdx.x;
    int b = blockIdx.z, ty = blockIdx.y, tx0 = blockIdx.x * 32;

    for (int i = tid; i < 1024; i += 128) {
        ((float*)s_kpe)[i] = g_kpe[i];
        ((float*)s_vpe)[i] = g_vpe[i];
    }
    __syncthreads();

    int w = tid >> 5, l = tid & 31;
    int c0 = l * 8;
    const float scale = 0.17677669529663687f;   // 32^-0.5

    float qb[8];
    ld8(qb, bq + c0);

    for (int it = 0; it < 8; it++) {
        int px = w * 8 + it;
        int tx = tx0 + px;
        const float* offp = offset + (((size_t)(b * 256 + ty) * 256 + tx) * 2);
        float fx = (float)tx + offp[0];          // offset[..., ::-1]
        float fy = (float)ty + offp[1];
        float flY = floorf(fy), flX = floorf(fx);
        float dy = fy - flY, dx = fx - flX;
        int iy = (int)flY, ix = (int)flX;

        size_t rb[4];
        #pragma unroll
        for (int uv = 0; uv < 4; uv++) {
            int hh = iy + (uv >> 1); hh = min(max(hh, 0), 255);
            int ww = ix + (uv & 1);  ww = min(max(ww, 0), 255);
            rb[uv] = ((size_t)b * HW + (size_t)(hh * 256 + ww)) * 768;
        }

        // q = mean_uv(Qf) + qpeY(dy) + qpeX(dx) + bq, scaled
        float uy = dy * (float)TABN; int gy = (int)uy; float ry = uy - (float)gy;
        float ux = dx * (float)TABN; int gx = (int)ux; float rx = ux - (float)gx;
        float q[8], tA[8], tB[8], tC[8], tD[8];
        ld8(tA, g_qpeY + gy * 256 + c0);
        ld8(tB, g_qpeY + (gy + 1) * 256 + c0);
        ld8(tC, g_qpeX + gx * 256 + c0);
        ld8(tD, g_qpeX + (gx + 1) * 256 + c0);
        #pragma unroll
        for (int j = 0; j < 8; j++)
            q[j] = qb[j] + tA[j] + ry * (tB[j] - tA[j]) + tC[j] + rx * (tD[j] - tC[j]);
        #pragma unroll
        for (int uv = 0; uv < 4; uv++) {
            float f[8];
            ld8(f, g_P + rb[uv] + c0);
            #pragma unroll
            for (int j = 0; j < 8; j++) q[j] = fmaf(0.25f, f[j], q[j]);
        }
        #pragma unroll
        for (int j = 0; j < 8; j++) q[j] *= scale;

        // logits (partial over this lane's 8 dims, then reduce over 4-lane head group)
        float lg[4];
        #pragma unroll
        for (int uv = 0; uv < 4; uv++) {
            float f[8], p[8];
            ld8(f, g_P + rb[uv] + 256 + c0);
            ld8(p, &s_kpe[uv][c0]);
            float s = 0.f;
            #pragma unroll
            for (int j = 0; j < 8; j++) s = fmaf(q[j], f[j] + p[j], s);
            lg[uv] = s;
        }
        #pragma unroll
        for (int uv = 0; uv < 4; uv++) lg[uv] += __shfl_xor_sync(0xffffffffu, lg[uv], 1);
        #pragma unroll
        for (int uv = 0; uv < 4; uv++) lg[uv] += __shfl_xor_sync(0xffffffffu, lg[uv], 2);

        // softmax over 4 window keys
        float mx = fmaxf(fmaxf(lg[0], lg[1]), fmaxf(lg[2], lg[3]));
        float e0 = __expf(lg[0] - mx), e1 = __expf(lg[1] - mx);
        float e2 = __expf(lg[2] - mx), e3 = __expf(lg[3] - mx);
        float inv = 1.0f / (e0 + e1 + e2 + e3);
        float at[4] = {e0 * inv, e1 * inv, e2 * inv, e3 * inv};

        // out = sum_uv attn * v
        float o[8];
        #pragma unroll
        for (int j = 0; j < 8; j++) o[j] = 0.f;
        #pragma unroll
        for (int uv = 0; uv < 4; uv++) {
            float f[8], p[8];
            ld8(f, g_P + rb[uv] + 512 + c0);
            ld8(p, &s_vpe[uv][c0]);
            #pragma unroll
            for (int j = 0; j < 8; j++) o[j] = fmaf(at[uv], f[j] + p[j], o[j]);
        }
        #pragma unroll
        for (int j = 0; j < 8; j++) s_out[(c0 + j) * 33 + px] = o[j];
    }
    __syncthreads();

    // coalesced transposed write: out[b, c, ty, tx0+px]
    for (int idx = tid; idx < 256 * 32; idx += 128) {
        int c = idx >> 5, px = idx & 31;
        out[((size_t)(b * 256 + c) * 256 + ty) * 256 + tx0 + px] = s_out[c * 33 + px];
    }
}

// ======================= launch =======================

extern "C" void kernel_launch(void* const* d_in, const int* in_sizes, int n_in,
                              void* d_out, int out_size) {
    (void)in_sizes; (void)n_in; (void)out_size;
    const float* feat   = (const float*)d_in[0];
    const float* offset = (const float*)d_in[1];
    const float* Wq     = (const float*)d_in[2];
    const float* bq     = (const float*)d_in[3];
    const float* Wk     = (const float*)d_in[4];
    const float* bk     = (const float*)d_in[5];
    const float* Wv     = (const float*)d_in[6];
    const float* bv     = (const float*)d_in[7];
    float* out = (float*)d_out;

    pack_wall_kernel<<<768, 256>>>(Wq, Wk, Wv);
    build_kvpe_kernel<<<4, 256>>>(Wk, bk, Wv, bv);
    build_qpetab_kernel<<<TABN + 1, 256>>>(Wq);
    proj_gemm_kernel<<<dim3(768 / GBN, HW / GBM, B_), 256>>>(feat);
    attn_epilogue_kernel<<<dim3(8, 256, B_), 128>>>(offset, bq, out);
}

// round 4
// speedup vs baseline: 1.0003x; 1.0003x over previous
#include <cuda_runtime.h>
#include <math.h>

#define B_   2
#define C_   256
#define HW   65536
#define TABN 2048

// ---- scratch (static __device__ arrays: allocation-free per harness rules) ----
__device__ float g_P[(size_t)B_ * HW * 768];      // per-source-pixel projections [b*HW][Qf|Kf|Vf]
__device__ float g_Wall[768 * 256];               // packed [Wq;Wk;Wv] row-major [j][c]
__device__ float g_kpe[4 * 256];                  // bk + pe_warp[uv]·Wk^T
__device__ float g_vpe[4 * 256];                  // bv + pe_warp[uv]·Wv^T
__device__ float g_qpeY[(TABN + 1) * 256];        // (pe_y(t)·Wq^T) lerp table
__device__ float g_qpeX[(TABN + 1) * 256];        // (pe_x(t)·Wq^T) lerp table

// ======================= prep kernels =======================

__global__ void pack_wall_kernel(const float* __restrict__ Wq,
                                 const float* __restrict__ Wk,
                                 const float* __restrict__ Wv) {
    int j = blockIdx.x;           // 0..767
    int c = threadIdx.x;          // 0..255
    const float* W = (j < 256) ? Wq : ((j < 512) ? Wk : Wv);
    g_Wall[j * 256 + c] = W[(j & 255) * 256 + c];
}

// pos_bias: sine PE of window coords (u,v) with card=(U-1,V-1)=(1,1); fold with bk/bv.
__global__ void build_kvpe_kernel(const float* __restrict__ Wk, const float* __restrict__ bk,
                                  const float* __restrict__ Wv, const float* __restrict__ bv) {
    int uv = blockIdx.x;          // 0..3 : (u = uv>>1 -> y, v = uv&1 -> x)
    int j  = threadIdx.x;         // 0..255
    __shared__ float pe[256];
    {
        int half = j >> 7;        // 0: y-half, 1: x-half
        int cc = j & 127;
        int m = cc >> 1;
        float coord = half ? (float)(uv & 1) : (float)(uv >> 1);
        float base = coord / (1.0f + 1e-6f) * 6.2831853071795864769f;
        float arg  = base * powf(10000.0f, -(float)(2 * m) / 128.0f);
        pe[j] = (cc & 1) ? cosf(arg) : sinf(arg);
    }
    __syncthreads();
    float sk = bk[j], sv = bv[j];
    const float* wkr = Wk + j * 256;
    const float* wvr = Wv + j * 256;
    #pragma unroll 4
    for (int c = 0; c < 256; c++) {
        float p = pe[c];
        sk = fmaf(p, wkr[c], sk);
        sv = fmaf(p, wvr[c], sv);
    }
    g_kpe[uv * 256 + j] = sk;
    g_vpe[uv * 256 + j] = sv;
}

// qpe tables: pe_curr uses card=(U,V)=(2,2) on the fractional offset t in [0,1].
// Table g in [0,TABN]; both halves use the identical pe(t) function, only Wq columns differ.
__global__ void build_qpetab_kernel(const float* __restrict__ Wq) {
    int g = blockIdx.x;           // 0..TABN
    int j = threadIdx.x;          // 0..255
    __shared__ float pe[128];
    if (j < 128) {
        int m = j >> 1;
        float t = (float)g / (float)TABN;
        float base = t / (2.0f + 1e-6f) * 6.2831853071795864769f;
        float arg  = base * powf(10000.0f, -(float)(2 * m) / 128.0f);
        pe[j] = (j & 1) ? cosf(arg) : sinf(arg);
    }
    __syncthreads();
    const float* wr = Wq + j * 256;
    float sy = 0.f, sx = 0.f;
    #pragma unroll 4
    for (int c = 0; c < 128; c++) {
        float p = pe[c];
        sy = fmaf(p, wr[c], sy);
        sx = fmaf(p, wr[128 + c], sx);
    }
    g_qpeY[g * 256 + j] = sy;
    g_qpeX[g * 256 + j] = sx;
}

// ======================= projection GEMM =======================
// P[b*HW + p][j] = sum_c feat[b][c][p] * Wall[j][c],  M=65536/batch, N=768, K=256.
// A is [C][HW] (p contiguous -> coalesced), B is Wall row-major.
#define GBM 128
#define GBN 128
#define GBK 8

__global__ void __launch_bounds__(256, 2) proj_gemm_kernel(const float* __restrict__ feat) {
    __shared__ float As[GBK][GBM];
    __shared__ float Bs[GBK][GBN];

    int b  = blockIdx.z;
    int m0 = blockIdx.y * GBM;
    int n0 = blockIdx.x * GBN;
    int tid = threadIdx.x;
    int tr = tid >> 4;            // 0..15
    int tc = tid & 15;            // 0..15

    float acc[8][8];
    #pragma unroll
    for (int i = 0; i < 8; i++)
        #pragma unroll
        for (int j = 0; j < 8; j++) acc[i][j] = 0.f;

    int la_r = tid >> 5;                 // 0..7  (c within k-tile)
    int la_c = (tid & 31) << 2;          // 0..124 (p)
    int lb_j = tid >> 1;                 // 0..127
    int lb_c = (tid & 1) << 2;           // 0 or 4

    const float* Aptr = feat + (size_t)b * C_ * HW + (size_t)la_r * HW + m0 + la_c;
    const float* Bptr = g_Wall + (size_t)(n0 + lb_j) * 256 + lb_c;

    for (int k0 = 0; k0 < 256; k0 += GBK) {
        float4 av = *(const float4*)(Aptr + (size_t)k0 * HW);
        *(float4*)&As[la_r][la_c] = av;
        float4 bv = *(const float4*)(Bptr + k0);
        Bs[lb_c + 0][lb_j] = bv.x;
        Bs[lb_c + 1][lb_j] = bv.y;
        Bs[lb_c + 2][lb_j] = bv.z;
        Bs[lb_c + 3][lb_j] = bv.w;
        __syncthreads();
        #pragma unroll
        for (int kk = 0; kk < GBK; kk++) {
            float a[8], bb[8];
            *(float4*)&a[0]  = *(const float4*)&As[kk][tr * 4];
            *(float4*)&a[4]  = *(const float4*)&As[kk][64 + tr * 4];
            *(float4*)&bb[0] = *(const float4*)&Bs[kk][tc * 4];
            *(float4*)&bb[4] = *(const float4*)&Bs[kk][64 + tc * 4];
            #pragma unroll
            for (int i = 0; i < 8; i++)
                #pragma unroll
                for (int j = 0; j < 8; j++)
                    acc[i][j] = fmaf(a[i], bb[j], acc[i][j]);
        }
        __syncthreads();
    }

    #pragma unroll
    for (int i = 0; i < 8; i++) {
        int mm = m0 + ((i < 4) ? (tr * 4 + i) : (64 + tr * 4 + (i - 4)));
        float* op = g_P + (size_t)(b * HW + mm) * 768 + n0;
        float4 v0 = make_float4(acc[i][0], acc[i][1], acc[i][2], acc[i][3]);
        float4 v1 = make_float4(acc[i][4], acc[i][5], acc[i][6], acc[i][7]);
        *(float4*)(op + tc * 4)      = v0;
        *(float4*)(op + 64 + tc * 4) = v1;
    }
}

// ======================= attention epilogue =======================
// 1 query vs 4 keys per target pixel. Warp: lane l owns channels [8l, 8l+8);
// head h = l/4 (lanes 4h..4h+3 cover its 32 dims -> 2-shfl logit reduction).

__device__ __forceinline__ void ld8(float* r, const float* p) {
    float4 v0 = *(const float4*)p;
    float4 v1 = *(const float4*)(p + 4);
    r[0] = v0.x; r[1] = v0.y; r[2] = v0.z; r[3] = v0.w;
    r[4] = v1.x; r[5] = v1.y; r[6] = v1.z; r[7] = v1.w;
}

__global__ void __launch_bounds__(128) attn_epilogue_kernel(
    const float* __restrict__ offset, const float* __restrict__ bq,
    float* __restrict__ out) {
    __shared__ float s_kpe[4][256];
    __shared__ float s_vpe[4][256];
    __shared__ float s_out[256 * 33];    // [channel][px], pitch 33 to dodge worst conflicts

    int tid = threadIdx.x;
    int b = blockIdx.z, ty = blockIdx.y, tx0 = blockIdx.x * 32;

    for (int i = tid; i < 1024; i += 128) {
        ((float*)s_kpe)[i] = g_kpe[i];
        ((float*)s_vpe)[i] = g_vpe[i];
    }
    __syncthreads();

    int w = tid >> 5, l = tid & 31;
    int c0 = l * 8;
    const float scale = 0.17677669529663687f;   // 32^-0.5

    float qb[8];
    ld8(qb, bq + c0);

    for (int it = 0; it < 8; it++) {
        int px = w * 8 + it;
        int tx = tx0 + px;
        const float* offp = offset + (((size_t)(b * 256 + ty) * 256 + tx) * 2);
        float fx = (float)tx + offp[0];          // offset[..., ::-1]
        float fy = (float)ty + offp[1];
        float flY = floorf(fy), flX = floorf(fx);
        float dy = fy - flY, dx = fx - flX;
        int iy = (int)flY, ix = (int)flX;

        size_t rb[4];
        #pragma unroll
        for (int uv = 0; uv < 4; uv++) {
            int hh = iy + (uv >> 1); hh = min(max(hh, 0), 255);
            int ww = ix + (uv & 1);  ww = min(max(ww, 0), 255);
            rb[uv] = ((size_t)b * HW + (size_t)(hh * 256 + ww)) * 768;
        }

        // q = mean_uv(Qf) + qpeY(dy) + qpeX(dx) + bq, scaled
        float uy = dy * (float)TABN; int gy = (int)uy; float ry = uy - (float)gy;
        float ux = dx * (float)TABN; int gx = (int)ux; float rx = ux - (float)gx;
        float q[8], tA[8], tB[8], tC[8], tD[8];
        ld8(tA, g_qpeY + gy * 256 + c0);
        ld8(tB, g_qpeY + (gy + 1) * 256 + c0);
        ld8(tC, g_qpeX + gx * 256 + c0);
        ld8(tD, g_qpeX + (gx + 1) * 256 + c0);
        #pragma unroll
        for (int j = 0; j < 8; j++)
            q[j] = qb[j] + tA[j] + ry * (tB[j] - tA[j]) + tC[j] + rx * (tD[j] - tC[j]);
        #pragma unroll
        for (int uv = 0; uv < 4; uv++) {
            float f[8];
            ld8(f, g_P + rb[uv] + c0);
            #pragma unroll
            for (int j = 0; j < 8; j++) q[j] = fmaf(0.25f, f[j], q[j]);
        }
        #pragma unroll
        for (int j = 0; j < 8; j++) q[j] *= scale;

        // logits (partial over this lane's 8 dims, then reduce over 4-lane head group)
        float lg[4];
        #pragma unroll
        for (int uv = 0; uv < 4; uv++) {
            float f[8], p[8];
            ld8(f, g_P + rb[uv] + 256 + c0);
            ld8(p, &s_kpe[uv][c0]);
            float s = 0.f;
            #pragma unroll
            for (int j = 0; j < 8; j++) s = fmaf(q[j], f[j] + p[j], s);
            lg[uv] = s;
        }
        #pragma unroll
        for (int uv = 0; uv < 4; uv++) lg[uv] += __shfl_xor_sync(0xffffffffu, lg[uv], 1);
        #pragma unroll
        for (int uv = 0; uv < 4; uv++) lg[uv] += __shfl_xor_sync(0xffffffffu, lg[uv], 2);

        // softmax over 4 window keys
        float mx = fmaxf(fmaxf(lg[0], lg[1]), fmaxf(lg[2], lg[3]));
        float e0 = __expf(lg[0] - mx), e1 = __expf(lg[1] - mx);
        float e2 = __expf(lg[2] - mx), e3 = __expf(lg[3] - mx);
        float inv = 1.0f / (e0 + e1 + e2 + e3);
        float at[4] = {e0 * inv, e1 * inv, e2 * inv, e3 * inv};

        // out = sum_uv attn * v
        float o[8];
        #pragma unroll
        for (int j = 0; j < 8; j++) o[j] = 0.f;
        #pragma unroll
        for (int uv = 0; uv < 4; uv++) {
            float f[8], p[8];
            ld8(f, g_P + rb[uv] + 512 + c0);
            ld8(p, &s_vpe[uv][c0]);
            #pragma unroll
            for (int j = 0; j < 8; j++) o[j] = fmaf(at[uv], f[j] + p[j], o[j]);
        }
        #pragma unroll
        for (int j = 0; j < 8; j++) s_out[(c0 + j) * 33 + px] = o[j];
    }
    __syncthreads();

    // coalesced transposed write: out[b, c, ty, tx0+px]
    for (int idx = tid; idx < 256 * 32; idx += 128) {
        int c = idx >> 5, px = idx & 31;
        out[((size_t)(b * 256 + c) * 256 + ty) * 256 + tx0 + px] = s_out[c * 33 + px];
    }
}

// ======================= launch =======================

extern "C" void kernel_launch(void* const* d_in, const int* in_sizes, int n_in,
                              void* d_out, int out_size) {
    (void)in_sizes; (void)n_in; (void)out_size;
    const float* feat   = (const float*)d_in[0];
    const float* offset = (const float*)d_in[1];
    const float* Wq     = (const float*)d_in[2];
    const float* bq     = (const float*)d_in[3];
    const float* Wk     = (const float*)d_in[4];
    const float* bk     = (const float*)d_in[5];
    const float* Wv     = (const float*)d_in[6];
    const float* bv     = (const float*)d_in[7];
    float* out = (float*)d_out;

    pack_wall_kernel<<<768, 256>>>(Wq, Wk, Wv);
    build_kvpe_kernel<<<4, 256>>>(Wk, bk, Wv, bv);
    build_qpetab_kernel<<<TABN + 1, 256>>>(Wq);
    proj_gemm_kernel<<<dim3(768 / GBN, HW / GBM, B_), 256>>>(feat);
    attn_epilogue_kernel<<<dim3(8, 256, B_), 128>>>(offset, bq, out);
}

// round 6
// speedup vs baseline: 1.3983x; 1.3979x over previous
#include <cuda_runtime.h>
#include <cuda_bf16.h>
#include <math.h>
#include <stdint.h>

#define B_   2
#define HW   65536
#define TABN 2048

// ---- scratch (static __device__ arrays: allocation-free) ----
__device__ float g_P[(size_t)B_ * HW * 768];              // [b*HW][Qf|Kf|Vf]
__device__ unsigned char g_Afmt[(size_t)1024 * 8 * 16384]; // feat, split+swizzled: [b*512+mblk][ch][128px][128B]
__device__ unsigned char g_Wfmt[(size_t)48 * 16384];       // weights, same layout: [jt*8+ch][128j][128B]
__device__ float g_kpe[4 * 256];
__device__ float g_vpe[4 * 256];
__device__ float g_qpeY[(TABN + 1) * 256];
__device__ float g_qpeX[(TABN + 1) * 256];

// ======================= helpers =======================

static __device__ __forceinline__ uint32_t smem_u32(const void* p) {
    uint32_t a;
    asm("{ .reg .u64 t; cvta.to.shared.u64 t, %1; cvt.u32.u64 %0, t; }" : "=r"(a) : "l"(p));
    return a;
}

static __device__ __forceinline__ void bsplit(float v, uint32_t& h, uint32_t& l) {
    __nv_bfloat16 hb = __float2bfloat16(v);
    float r = v - __bfloat162float(hb);
    __nv_bfloat16 lb = __float2bfloat16(r);
    h = (uint32_t)*(uint16_t*)&hb;
    l = (uint32_t)*(uint16_t*)&lb;
}

static __device__ __forceinline__ void cp16(uint32_t dst, const void* src) {
    asm volatile("cp.async.cg.shared.global [%0], [%1], 16;" :: "r"(dst), "l"(src));
}
#define CP_COMMIT() asm volatile("cp.async.commit_group;" ::: "memory")

static __device__ __forceinline__ void ldsm4(uint32_t* r, uint32_t addr) {
    asm volatile("ldmatrix.sync.aligned.m8n8.x4.shared.b16 {%0,%1,%2,%3}, [%4];"
                 : "=r"(r[0]), "=r"(r[1]), "=r"(r[2]), "=r"(r[3]) : "r"(addr));
}

static __device__ __forceinline__ void mma16816(float* d, const uint32_t* a,
                                                uint32_t b0, uint32_t b1) {
    asm volatile(
        "mma.sync.aligned.m16n8k16.row.col.f32.bf16.bf16.f32 "
        "{%0,%1,%2,%3}, {%4,%5,%6,%7}, {%8,%9}, {%0,%1,%2,%3};"
        : "+f"(d[0]), "+f"(d[1]), "+f"(d[2]), "+f"(d[3])
        : "r"(a[0]), "r"(a[1]), "r"(a[2]), "r"(a[3]), "r"(b0), "r"(b1));
}

// ======================= prestage kernels =======================
// Layout per (tileblock, chunk): 128 rows x 128B. Row r: bytes 0-63 = h(32 k, bf16),
// bytes 64-127 = l(32 k). 16B unit u within row stored at u ^ (r & 7)  (SW128).

__global__ void prestage_feat_kernel(const float* __restrict__ feat) {
    int mblk = blockIdx.x, ch = blockIdx.y, b = blockIdx.z;
    __shared__ float tile[32][132];
    int tid = threadIdx.x;
    const float* src = feat + ((size_t)b * 256 + ch * 32) * HW + mblk * 128;
    #pragma unroll
    for (int p = 0; p < 4; p++) {
        int t = p * 256 + tid;
        int c = t >> 5, pxq = t & 31;
        float4 v = *(const float4*)(src + (size_t)c * HW + pxq * 4);
        *(float4*)&tile[c][pxq * 4] = v;
    }
    __syncthreads();

    int w = tid >> 5, l = tid & 31;
    unsigned char* dst = g_Afmt + ((((size_t)(b * 512 + mblk)) * 8 + ch) << 14);
    uint32_t uh = (uint32_t)(w >> 1);
    uint32_t half = (uint32_t)(w & 1) * 8;
    #pragma unroll
    for (int p = 0; p < 4; p++) {
        int px = p * 32 + l;
        float v0 = tile[w * 4 + 0][px], v1 = tile[w * 4 + 1][px];
        float v2 = tile[w * 4 + 2][px], v3 = tile[w * 4 + 3][px];
        uint32_t h0, l0, h1, l1, h2, l2, h3, l3;
        bsplit(v0, h0, l0); bsplit(v1, h1, l1);
        bsplit(v2, h2, l2); bsplit(v3, h3, l3);
        uint2 hp = make_uint2(h0 | (h1 << 16), h2 | (h3 << 16));
        uint2 lp = make_uint2(l0 | (l1 << 16), l2 | (l3 << 16));
        uint32_t rb = (uint32_t)px * 128;
        uint32_t sw = (uint32_t)(px & 7);
        *(uint2*)(dst + rb + (((uh       ^ sw) << 4) + half)) = hp;
        *(uint2*)(dst + rb + ((((uh + 4) ^ sw) << 4) + half)) = lp;
    }
}

__global__ void prestage_w_kernel(const float* __restrict__ Wq,
                                  const float* __restrict__ Wk,
                                  const float* __restrict__ Wv) {
    int jt = blockIdx.x, ch = blockIdx.y;
    const float* W = (jt < 2) ? Wq : ((jt < 4) ? Wk : Wv);
    int jrb = (jt & 1) * 128;
    int tid = threadIdx.x;
    int j = tid >> 1, kh = tid & 1;
    const float* src = W + (size_t)(jrb + j) * 256 + ch * 32 + kh * 16;
    unsigned char* dst = g_Wfmt + (((size_t)jt * 8 + ch) << 14) + j * 128;
    uint32_t sw = (uint32_t)(j & 7);
    #pragma unroll
    for (int q = 0; q < 4; q++) {
        float4 v = *(const float4*)(src + q * 4);
        uint32_t h0, l0, h1, l1, h2, l2, h3, l3;
        bsplit(v.x, h0, l0); bsplit(v.y, h1, l1);
        bsplit(v.z, h2, l2); bsplit(v.w, h3, l3);
        int q8 = kh * 4 + q;
        uint32_t u = (uint32_t)(q8 >> 1);
        uint32_t half = (uint32_t)(q8 & 1) * 8;
        *(uint2*)(dst + (((u       ^ sw) << 4) + half)) = make_uint2(h0 | (h1 << 16), h2 | (h3 << 16));
        *(uint2*)(dst + ((((u + 4) ^ sw) << 4) + half)) = make_uint2(l0 | (l1 << 16), l2 | (l3 << 16));
    }
}

// ======================= prep kernels (unchanged, passing) =======================

__global__ void build_kvpe_kernel(const float* __restrict__ Wk, const float* __restrict__ bk,
                                  const float* __restrict__ Wv, const float* __restrict__ bv) {
    int uv = blockIdx.x;
    int j  = threadIdx.x;
    __shared__ float pe[256];
    {
        int half = j >> 7;
        int cc = j & 127;
        int m = cc >> 1;
        float coord = half ? (float)(uv & 1) : (float)(uv >> 1);
        float base = coord / (1.0f + 1e-6f) * 6.2831853071795864769f;
        float arg  = base * powf(10000.0f, -(float)(2 * m) / 128.0f);
        pe[j] = (cc & 1) ? cosf(arg) : sinf(arg);
    }
    __syncthreads();
    float sk = bk[j], sv = bv[j];
    const float* wkr = Wk + j * 256;
    const float* wvr = Wv + j * 256;
    #pragma unroll 4
    for (int c = 0; c < 256; c++) {
        float p = pe[c];
        sk = fmaf(p, wkr[c], sk);
        sv = fmaf(p, wvr[c], sv);
    }
    g_kpe[uv * 256 + j] = sk;
    g_vpe[uv * 256 + j] = sv;
}

__global__ void build_qpetab_kernel(const float* __restrict__ Wq) {
    int g = blockIdx.x;
    int j = threadIdx.x;
    __shared__ float pe[128];
    if (j < 128) {
        int m = j >> 1;
        float t = (float)g / (float)TABN;
        float base = t / (2.0f + 1e-6f) * 6.2831853071795864769f;
        float arg  = base * powf(10000.0f, -(float)(2 * m) / 128.0f);
        pe[j] = (j & 1) ? cosf(arg) : sinf(arg);
    }
    __syncthreads();
    const float* wr = Wq + j * 256;
    float sy = 0.f, sx = 0.f;
    #pragma unroll 4
    for (int c = 0; c < 128; c++) {
        float p = pe[c];
        sy = fmaf(p, wr[c], sy);
        sx = fmaf(p, wr[128 + c], sx);
    }
    g_qpeY[g * 256 + j] = sy;
    g_qpeX[g * 256 + j] = sx;
}

// ======================= bf16x3 mma.sync projection GEMM =======================
// D[px 0..127][j 0..127] = sum_c feat[px][c] * W[j][c]; 8 chunks of k=32, cp.async double-buffer.
// Warp layout: wm = wid&1 (64 px), wn = wid>>1 (32 j); warp tile 64x32 = 4x4 m16n8 mma tiles.

#define SMEM_MMA 65536

__global__ void __launch_bounds__(256) proj_mma2_kernel(int dummy) {
    extern __shared__ char sm[];
    uint32_t smb = smem_u32(sm);
    int tid = threadIdx.x;
    int wid = tid >> 5, l = tid & 31;
    int wm = wid & 1, wn = wid >> 1;
    int jt = blockIdx.x, mblk = blockIdx.y, b = blockIdx.z;

    const unsigned char* Ag = g_Afmt + ((((size_t)(b * 512 + mblk)) * 8) << 14);
    const unsigned char* Bg = g_Wfmt + (((size_t)jt * 8) << 14);

    float d[4][4][4];
    #pragma unroll
    for (int i = 0; i < 4; i++)
        #pragma unroll
        for (int j = 0; j < 4; j++)
            #pragma unroll
            for (int k = 0; k < 4; k++) d[i][j][k] = 0.f;

    // ---- copy chunk ch into buffer buf ----
    #define COPY_CHUNK(ch, buf) do {                                            \
        uint32_t _dA = smb + (buf) * 32768;                                     \
        uint32_t _dB = _dA + 16384;                                             \
        const unsigned char* _sA = Ag + ((size_t)(ch) << 14);                   \
        const unsigned char* _sB = Bg + ((size_t)(ch) << 14);                   \
        _Pragma("unroll")                                                       \
        for (int q = 0; q < 4; q++) {                                           \
            cp16(_dA + tid * 16 + q * 4096, _sA + tid * 16 + q * 4096);         \
            cp16(_dB + tid * 16 + q * 4096, _sB + tid * 16 + q * 4096);         \
        }                                                                       \
    } while (0)

    COPY_CHUNK(0, 0); CP_COMMIT();
    COPY_CHUNK(1, 1); CP_COMMIT();

    int ch16 = l >> 4;          // 0/1: k-halves for ldmatrix
    int r16 = l & 15;

    for (int ch = 0; ch < 8; ch++) {
        int buf = ch & 1;
        if (ch == 7) { asm volatile("cp.async.wait_group 0;" ::: "memory"); }
        else         { asm volatile("cp.async.wait_group 1;" ::: "memory"); }
        __syncthreads();

        uint32_t aB = smb + buf * 32768;
        uint32_t bB = aB + 16384;

        #pragma unroll
        for (int s = 0; s < 2; s++) {
            uint32_t ah[4][4], al[4][4];
            #pragma unroll
            for (int mt = 0; mt < 4; mt++) {
                int row = wm * 64 + mt * 16 + r16;
                uint32_t rb = aB + row * 128;
                uint32_t sw = (uint32_t)(row & 7);
                ldsm4(ah[mt], rb + ((((uint32_t)(s * 2 + ch16)    ) ^ sw) << 4));
                ldsm4(al[mt], rb + ((((uint32_t)(4 + s * 2 + ch16)) ^ sw) << 4));
            }
            #pragma unroll
            for (int ntp = 0; ntp < 2; ntp++) {
                int row = wn * 32 + ntp * 16 + r16;
                uint32_t rb = bB + row * 128;
                uint32_t sw = (uint32_t)(row & 7);
                uint32_t bh[4], bl[4];
                ldsm4(bh, rb + ((((uint32_t)(s * 2 + ch16)    ) ^ sw) << 4));
                ldsm4(bl, rb + ((((uint32_t)(4 + s * 2 + ch16)) ^ sw) << 4));
                #pragma unroll
                for (int sub = 0; sub < 2; sub++) {
                    int nt = ntp * 2 + sub;
                    uint32_t b0h = bh[sub], b1h = bh[2 + sub];
                    uint32_t b0l = bl[sub], b1l = bl[2 + sub];
                    #pragma unroll
                    for (int mt = 0; mt < 4; mt++) {
                        mma16816(d[mt][nt], ah[mt], b0h, b1h);
                        mma16816(d[mt][nt], al[mt], b0h, b1h);
                        mma16816(d[mt][nt], ah[mt], b0l, b1l);
                    }
                }
            }
        }
        __syncthreads();
        if (ch + 2 < 8) { COPY_CHUNK(ch + 2, buf); CP_COMMIT(); }
    }

    // ---- write D to g_P ----
    int rA = wm * 64 + (l >> 2);
    int colb = jt * 128 + wn * 32 + (l & 3) * 2;
    #pragma unroll
    for (int mt = 0; mt < 4; mt++) {
        #pragma unroll
        for (int nt = 0; nt < 4; nt++) {
            float* p0 = g_P + (size_t)(b * HW + mblk * 128 + rA + mt * 16) * 768 + colb + nt * 8;
            *(float2*)p0 = make_float2(d[mt][nt][0], d[mt][nt][1]);
            *(float2*)(p0 + 8 * 768) = make_float2(d[mt][nt][2], d[mt][nt][3]);
        }
    }
    (void)dummy;
}

// ======================= attention epilogue (unchanged, passing) =======================

static __device__ __forceinline__ void ld8(float* r, const float* p) {
    float4 v0 = *(const float4*)p;
    float4 v1 = *(const float4*)(p + 4);
    r[0] = v0.x; r[1] = v0.y; r[2] = v0.z; r[3] = v0.w;
    r[4] = v1.x; r[5] = v1.y; r[6] = v1.z; r[7] = v1.w;
}

__global__ void __launch_bounds__(256) attn_epilogue_kernel(
    const float* __restrict__ offset, const float* __restrict__ bq,
    float* __restrict__ out) {
    __shared__ float s_kpe[4][256];
    __shared__ float s_vpe[4][256];
    __shared__ float s_out[256 * 33];

    int tid = threadIdx.x;
    int b = blockIdx.z, ty = blockIdx.y, tx0 = blockIdx.x * 32;

    for (int i = tid; i < 1024; i += 256) {
        ((float*)s_kpe)[i] = g_kpe[i];
        ((float*)s_vpe)[i] = g_vpe[i];
    }
    __syncthreads();

    int w = tid >> 5, l = tid & 31;
    int c0 = l * 8;
    const float scale = 0.17677669529663687f;   // 32^-0.5

    float qb[8];
    ld8(qb, bq + c0);

    for (int it = 0; it < 4; it++) {
        int px = w * 4 + it;
        int tx = tx0 + px;
        const float* offp = offset + (((size_t)(b * 256 + ty) * 256 + tx) * 2);
        float fx = (float)tx + offp[0];
        float fy = (float)ty + offp[1];
        float flY = floorf(fy), flX = floorf(fx);
        float dy = fy - flY, dx = fx - flX;
        int iy = (int)flY, ix = (int)flX;

        size_t rb[4];
        #pragma unroll
        for (int uv = 0; uv < 4; uv++) {
            int hh = iy + (uv >> 1); hh = min(max(hh, 0), 255);
            int ww = ix + (uv & 1);  ww = min(max(ww, 0), 255);
            rb[uv] = ((size_t)b * HW + (size_t)(hh * 256 + ww)) * 768;
        }

        float uy = dy * (float)TABN; int gy = (int)uy; float ry = uy - (float)gy;
        float ux = dx * (float)TABN; int gx = (int)ux; float rx = ux - (float)gx;
        float q[8], tA[8], tB[8], tC[8], tD[8];
        ld8(tA, g_qpeY + gy * 256 + c0);
        ld8(tB, g_qpeY + (gy + 1) * 256 + c0);
        ld8(tC, g_qpeX + gx * 256 + c0);
        ld8(tD, g_qpeX + (gx + 1) * 256 + c0);
        #pragma unroll
        for (int j = 0; j < 8; j++)
            q[j] = qb[j] + tA[j] + ry * (tB[j] - tA[j]) + tC[j] + rx * (tD[j] - tC[j]);
        #pragma unroll
        for (int uv = 0; uv < 4; uv++) {
            float f[8];
            ld8(f, g_P + rb[uv] + c0);
            #pragma unroll
            for (int j = 0; j < 8; j++) q[j] = fmaf(0.25f, f[j], q[j]);
        }
        #pragma unroll
        for (int j = 0; j < 8; j++) q[j] *= scale;

        float lg[4];
        #pragma unroll
        for (int uv = 0; uv < 4; uv++) {
            float f[8], p[8];
            ld8(f, g_P + rb[uv] + 256 + c0);
            ld8(p, &s_kpe[uv][c0]);
            float s = 0.f;
            #pragma unroll
            for (int j = 0; j < 8; j++) s = fmaf(q[j], f[j] + p[j], s);
            lg[uv] = s;
        }
        #pragma unroll
        for (int uv = 0; uv < 4; uv++) lg[uv] += __shfl_xor_sync(0xffffffffu, lg[uv], 1);
        #pragma unroll
        for (int uv = 0; uv < 4; uv++) lg[uv] += __shfl_xor_sync(0xffffffffu, lg[uv], 2);

        float mx = fmaxf(fmaxf(lg[0], lg[1]), fmaxf(lg[2], lg[3]));
        float e0 = __expf(lg[0] - mx), e1 = __expf(lg[1] - mx);
        float e2 = __expf(lg[2] - mx), e3 = __expf(lg[3] - mx);
        float inv = 1.0f / (e0 + e1 + e2 + e3);
        float at[4] = {e0 * inv, e1 * inv, e2 * inv, e3 * inv};

        float o[8];
        #pragma unroll
        for (int j = 0; j < 8; j++) o[j] = 0.f;
        #pragma unroll
        for (int uv = 0; uv < 4; uv++) {
            float f[8], p[8];
            ld8(f, g_P + rb[uv] + 512 + c0);
            ld8(p, &s_vpe[uv][c0]);
            #pragma unroll
            for (int j = 0; j < 8; j++) o[j] = fmaf(at[uv], f[j] + p[j], o[j]);
        }
        #pragma unroll
        for (int j = 0; j < 8; j++) s_out[(c0 + j) * 33 + px] = o[j];
    }
    __syncthreads();

    for (int idx = tid; idx < 256 * 32; idx += 256) {
        int c = idx >> 5, px = idx & 31;
        out[((size_t)(b * 256 + c) * 256 + ty) * 256 + tx0 + px] = s_out[c * 33 + px];
    }
}

// ======================= launch =======================

extern "C" void kernel_launch(void* const* d_in, const int* in_sizes, int n_in,
                              void* d_out, int out_size) {
    (void)in_sizes; (void)n_in; (void)out_size;
    const float* feat   = (const float*)d_in[0];
    const float* offset = (const float*)d_in[1];
    const float* Wq     = (const float*)d_in[2];
    const float* bq     = (const float*)d_in[3];
    const float* Wk     = (const float*)d_in[4];
    const float* bk     = (const float*)d_in[5];
    const float* Wv     = (const float*)d_in[6];
    const float* bv     = (const float*)d_in[7];
    float* out = (float*)d_out;

    static int attr_set = 0;
    if (!attr_set) {
        cudaFuncSetAttribute(proj_mma2_kernel,
                             cudaFuncAttributeMaxDynamicSharedMemorySize, SMEM_MMA);
        attr_set = 1;
    }

    prestage_w_kernel<<<dim3(6, 8), 256>>>(Wq, Wk, Wv);
    prestage_feat_kernel<<<dim3(512, 8, B_), 256>>>(feat);
    build_kvpe_kernel<<<4, 256>>>(Wk, bk, Wv, bv);
    build_qpetab_kernel<<<TABN + 1, 256>>>(Wq);
    proj_mma2_kernel<<<dim3(6, 512, B_), 256, SMEM_MMA>>>(0);
    attn_epilogue_kernel<<<dim3(8, 256, B_), 256>>>(offset, bq, out);
}

// round 7
// speedup vs baseline: 2.1167x; 1.5138x over previous
#include <cuda_runtime.h>
#include <cuda_bf16.h>
#include <math.h>
#include <stdint.h>

#define B_   2
#define HW   65536
#define TABN 2048

// ---- scratch (static __device__ arrays: allocation-free) ----
__device__ float g_P[(size_t)B_ * HW * 768];              // [b*HW][Qf|Kf|Vf]
__device__ unsigned char g_Afmt[(size_t)1024 * 8 * 16384]; // feat, split+swizzled: [b*512+mblk][ch][128px][128B]
__device__ unsigned char g_Wfmt[(size_t)48 * 16384];       // weights, same layout: [jt*8+ch][128j][128B]
__device__ float g_kpe[4 * 256];
__device__ float g_vpe[4 * 256];
__device__ float g_qpeY[(TABN + 1) * 256];
__device__ float g_qpeX[(TABN + 1) * 256];

// ======================= helpers =======================

static __device__ __forceinline__ uint32_t smem_u32(const void* p) {
    uint32_t a;
    asm("{ .reg .u64 t; cvta.to.shared.u64 t, %1; cvt.u32.u64 %0, t; }" : "=r"(a) : "l"(p));
    return a;
}

static __device__ __forceinline__ void bsplit(float v, uint32_t& h, uint32_t& l) {
    __nv_bfloat16 hb = __float2bfloat16(v);
    float r = v - __bfloat162float(hb);
    __nv_bfloat16 lb = __float2bfloat16(r);
    h = (uint32_t)*(uint16_t*)&hb;
    l = (uint32_t)*(uint16_t*)&lb;
}

static __device__ __forceinline__ void cp16(uint32_t dst, const void* src) {
    asm volatile("cp.async.cg.shared.global [%0], [%1], 16;" :: "r"(dst), "l"(src));
}
#define CP_COMMIT() asm volatile("cp.async.commit_group;" ::: "memory")

static __device__ __forceinline__ void ldsm4(uint32_t* r, uint32_t addr) {
    asm volatile("ldmatrix.sync.aligned.m8n8.x4.shared.b16 {%0,%1,%2,%3}, [%4];"
                 : "=r"(r[0]), "=r"(r[1]), "=r"(r[2]), "=r"(r[3]) : "r"(addr));
}

static __device__ __forceinline__ void mma16816(float* d, const uint32_t* a,
                                                uint32_t b0, uint32_t b1) {
    asm volatile(
        "mma.sync.aligned.m16n8k16.row.col.f32.bf16.bf16.f32 "
        "{%0,%1,%2,%3}, {%4,%5,%6,%7}, {%8,%9}, {%0,%1,%2,%3};"
        : "+f"(d[0]), "+f"(d[1]), "+f"(d[2]), "+f"(d[3])
        : "r"(a[0]), "r"(a[1]), "r"(a[2]), "r"(a[3]), "r"(b0), "r"(b1));
}

// ======================= prestage kernels =======================
// Layout per (tileblock, chunk): 128 rows x 128B. Row r: bytes 0-63 = h(32 k, bf16),
// bytes 64-127 = l(32 k). 16B unit u within row stored at u ^ (r & 7)  (SW128).

__global__ void prestage_feat_kernel(const float* __restrict__ feat) {
    int mblk = blockIdx.x, ch = blockIdx.y, b = blockIdx.z;
    __shared__ float tile[32][132];
    int tid = threadIdx.x;
    const float* src = feat + ((size_t)b * 256 + ch * 32) * HW + mblk * 128;
    #pragma unroll
    for (int p = 0; p < 4; p++) {
        int t = p * 256 + tid;
        int c = t >> 5, pxq = t & 31;
        float4 v = *(const float4*)(src + (size_t)c * HW + pxq * 4);
        *(float4*)&tile[c][pxq * 4] = v;
    }
    __syncthreads();

    int w = tid >> 5, l = tid & 31;
    unsigned char* dst = g_Afmt + ((((size_t)(b * 512 + mblk)) * 8 + ch) << 14);
    uint32_t uh = (uint32_t)(w >> 1);
    uint32_t half = (uint32_t)(w & 1) * 8;
    #pragma unroll
    for (int p = 0; p < 4; p++) {
        int px = p * 32 + l;
        float v0 = tile[w * 4 + 0][px], v1 = tile[w * 4 + 1][px];
        float v2 = tile[w * 4 + 2][px], v3 = tile[w * 4 + 3][px];
        uint32_t h0, l0, h1, l1, h2, l2, h3, l3;
        bsplit(v0, h0, l0); bsplit(v1, h1, l1);
        bsplit(v2, h2, l2); bsplit(v3, h3, l3);
        uint2 hp = make_uint2(h0 | (h1 << 16), h2 | (h3 << 16));
        uint2 lp = make_uint2(l0 | (l1 << 16), l2 | (l3 << 16));
        uint32_t rb = (uint32_t)px * 128;
        uint32_t sw = (uint32_t)(px & 7);
        *(uint2*)(dst + rb + (((uh       ^ sw) << 4) + half)) = hp;
        *(uint2*)(dst + rb + ((((uh + 4) ^ sw) << 4) + half)) = lp;
    }
}

__global__ void prestage_w_kernel(const float* __restrict__ Wq,
                                  const float* __restrict__ Wk,
                                  const float* __restrict__ Wv) {
    int jt = blockIdx.x, ch = blockIdx.y;
    const float* W = (jt < 2) ? Wq : ((jt < 4) ? Wk : Wv);
    int jrb = (jt & 1) * 128;
    int tid = threadIdx.x;
    int j = tid >> 1, kh = tid & 1;
    const float* src = W + (size_t)(jrb + j) * 256 + ch * 32 + kh * 16;
    unsigned char* dst = g_Wfmt + (((size_t)jt * 8 + ch) << 14) + j * 128;
    uint32_t sw = (uint32_t)(j & 7);
    #pragma unroll
    for (int q = 0; q < 4; q++) {
        float4 v = *(const float4*)(src + q * 4);
        uint32_t h0, l0, h1, l1, h2, l2, h3, l3;
        bsplit(v.x, h0, l0); bsplit(v.y, h1, l1);
        bsplit(v.z, h2, l2); bsplit(v.w, h3, l3);
        int q8 = kh * 4 + q;
        uint32_t u = (uint32_t)(q8 >> 1);
        uint32_t half = (uint32_t)(q8 & 1) * 8;
        *(uint2*)(dst + (((u       ^ sw) << 4) + half)) = make_uint2(h0 | (h1 << 16), h2 | (h3 << 16));
        *(uint2*)(dst + ((((u + 4) ^ sw) << 4) + half)) = make_uint2(l0 | (l1 << 16), l2 | (l3 << 16));
    }
}

// ======================= prep kernels =======================

__global__ void build_kvpe_kernel(const float* __restrict__ Wk, const float* __restrict__ bk,
                                  const float* __restrict__ Wv, const float* __restrict__ bv) {
    int uv = blockIdx.x;
    int j  = threadIdx.x;
    __shared__ float pe[256];
    {
        int half = j >> 7;
        int cc = j & 127;
        int m = cc >> 1;
        float coord = half ? (float)(uv & 1) : (float)(uv >> 1);
        float base = coord / (1.0f + 1e-6f) * 6.2831853071795864769f;
        float arg  = base * powf(10000.0f, -(float)(2 * m) / 128.0f);
        pe[j] = (cc & 1) ? cosf(arg) : sinf(arg);
    }
    __syncthreads();
    float sk = bk[j], sv = bv[j];
    const float* wkr = Wk + j * 256;
    const float* wvr = Wv + j * 256;
    #pragma unroll 4
    for (int c = 0; c < 256; c++) {
        float p = pe[c];
        sk = fmaf(p, wkr[c], sk);
        sv = fmaf(p, wvr[c], sv);
    }
    g_kpe[uv * 256 + j] = sk;
    g_vpe[uv * 256 + j] = sv;
}

// qpe tables as a tiled GEMM: qpe{Y,X}[g][j] = sum_c pe[g][c] * Wq[j][half*128 + c].
// Grid: x = 65 blocks of 32 g-rows, y = 4 n-blocks of 128 (Y rows 0-127, Y 128-255,
// X 0-127, X 128-255). K = 128 staged in 4 chunks of 32.
__global__ void __launch_bounds__(256) qpetab_gemm_kernel(const float* __restrict__ Wq) {
    __shared__ float pe[32][132];
    __shared__ float Bs[32][128];

    int tid = threadIdx.x;
    int g0 = blockIdx.x * 32;
    int n0 = blockIdx.y * 128;
    int half = n0 >> 8;            // 0 -> Y table, 1 -> X table
    int jbase = n0 & 255;          // Wq row base for this n-block

    // compute pe tile [32 g][128 c]
    for (int i = tid; i < 32 * 128; i += 256) {
        int gg = i >> 7, c = i & 127;
        int m = c >> 1;
        float t = (float)(g0 + gg) / (float)TABN;
        float base = t / (2.0f + 1e-6f) * 6.2831853071795864769f;
        float arg  = base * powf(10000.0f, -(float)(2 * m) / 128.0f);
        pe[gg][c] = (c & 1) ? cosf(arg) : sinf(arg);
    }
    __syncthreads();

    int gthr = tid >> 5;           // 0..7 -> 4 g rows each
    int nthr = tid & 31;           // 0..31 -> 4 n cols each
    float acc[4][4];
    #pragma unroll
    for (int i = 0; i < 4; i++)
        #pragma unroll
        for (int j = 0; j < 4; j++) acc[i][j] = 0.f;

    int lj = tid >> 1, lkq = (tid & 1) * 16;   // B loader: row j, k-quarter
    const float* wsrc = Wq + (size_t)(jbase + lj) * 256 + half * 128 + lkq;

    for (int k0 = 0; k0 < 128; k0 += 32) {
        #pragma unroll
        for (int q = 0; q < 4; q++) {
            float4 v = *(const float4*)(wsrc + k0 + q * 4);
            Bs[lkq + q * 4 + 0][lj] = v.x;
            Bs[lkq + q * 4 + 1][lj] = v.y;
            Bs[lkq + q * 4 + 2][lj] = v.z;
            Bs[lkq + q * 4 + 3][lj] = v.w;
        }
        __syncthreads();
        #pragma unroll
        for (int kk = 0; kk < 32; kk++) {
            float a[4], b[4];
            #pragma unroll
            for (int i = 0; i < 4; i++) a[i] = pe[gthr * 4 + i][k0 + kk];
            *(float4*)&b[0] = *(const float4*)&Bs[kk][nthr * 4];
            #pragma unroll
            for (int i = 0; i < 4; i++)
                #pragma unroll
                for (int j = 0; j < 4; j++)
                    acc[i][j] = fmaf(a[i], b[j], acc[i][j]);
        }
        __syncthreads();
    }

    float* dst = half ? g_qpeX : g_qpeY;
    #pragma unroll
    for (int i = 0; i < 4; i++) {
        int g = g0 + gthr * 4 + i;
        if (g <= TABN) {
            *(float4*)&dst[(size_t)g * 256 + jbase + nthr * 4] =
                make_float4(acc[i][0], acc[i][1], acc[i][2], acc[i][3]);
        }
    }
}

// ======================= bf16x3 mma.sync projection GEMM =======================

#define SMEM_MMA 65536

__global__ void __launch_bounds__(256) proj_mma2_kernel(int dummy) {
    extern __shared__ char sm[];
    uint32_t smb = smem_u32(sm);
    int tid = threadIdx.x;
    int wid = tid >> 5, l = tid & 31;
    int wm = wid & 1, wn = wid >> 1;
    int jt = blockIdx.x, mblk = blockIdx.y, b = blockIdx.z;

    const unsigned char* Ag = g_Afmt + ((((size_t)(b * 512 + mblk)) * 8) << 14);
    const unsigned char* Bg = g_Wfmt + (((size_t)jt * 8) << 14);

    float d[4][4][4];
    #pragma unroll
    for (int i = 0; i < 4; i++)
        #pragma unroll
        for (int j = 0; j < 4; j++)
            #pragma unroll
            for (int k = 0; k < 4; k++) d[i][j][k] = 0.f;

    #define COPY_CHUNK(ch, buf) do {                                            \
        uint32_t _dA = smb + (buf) * 32768;                                     \
        uint32_t _dB = _dA + 16384;                                             \
        const unsigned char* _sA = Ag + ((size_t)(ch) << 14);                   \
        const unsigned char* _sB = Bg + ((size_t)(ch) << 14);                   \
        _Pragma("unroll")                                                       \
        for (int q = 0; q < 4; q++) {                                           \
            cp16(_dA + tid * 16 + q * 4096, _sA + tid * 16 + q * 4096);         \
            cp16(_dB + tid * 16 + q * 4096, _sB + tid * 16 + q * 4096);         \
        }                                                                       \
    } while (0)

    COPY_CHUNK(0, 0); CP_COMMIT();
    COPY_CHUNK(1, 1); CP_COMMIT();

    int ch16 = l >> 4;
    int r16 = l & 15;

    for (int ch = 0; ch < 8; ch++) {
        int buf = ch & 1;
        if (ch == 7) { asm volatile("cp.async.wait_group 0;" ::: "memory"); }
        else         { asm volatile("cp.async.wait_group 1;" ::: "memory"); }
        __syncthreads();

        uint32_t aB = smb + buf * 32768;
        uint32_t bB = aB + 16384;

        #pragma unroll
        for (int s = 0; s < 2; s++) {
            uint32_t ah[4][4], al[4][4];
            #pragma unroll
            for (int mt = 0; mt < 4; mt++) {
                int row = wm * 64 + mt * 16 + r16;
                uint32_t rb = aB + row * 128;
                uint32_t sw = (uint32_t)(row & 7);
                ldsm4(ah[mt], rb + ((((uint32_t)(s * 2 + ch16)    ) ^ sw) << 4));
                ldsm4(al[mt], rb + ((((uint32_t)(4 + s * 2 + ch16)) ^ sw) << 4));
            }
            #pragma unroll
            for (int ntp = 0; ntp < 2; ntp++) {
                int row = wn * 32 + ntp * 16 + r16;
                uint32_t rb = bB + row * 128;
                uint32_t sw = (uint32_t)(row & 7);
                uint32_t bh[4], bl[4];
                ldsm4(bh, rb + ((((uint32_t)(s * 2 + ch16)    ) ^ sw) << 4));
                ldsm4(bl, rb + ((((uint32_t)(4 + s * 2 + ch16)) ^ sw) << 4));
                #pragma unroll
                for (int sub = 0; sub < 2; sub++) {
                    int nt = ntp * 2 + sub;
                    uint32_t b0h = bh[sub], b1h = bh[2 + sub];
                    uint32_t b0l = bl[sub], b1l = bl[2 + sub];
                    #pragma unroll
                    for (int mt = 0; mt < 4; mt++) {
                        mma16816(d[mt][nt], ah[mt], b0h, b1h);
                        mma16816(d[mt][nt], al[mt], b0h, b1h);
                        mma16816(d[mt][nt], ah[mt], b0l, b1l);
                    }
                }
            }
        }
        __syncthreads();
        if (ch + 2 < 8) { COPY_CHUNK(ch + 2, buf); CP_COMMIT(); }
    }

    int rA = wm * 64 + (l >> 2);
    int colb = jt * 128 + wn * 32 + (l & 3) * 2;
    #pragma unroll
    for (int mt = 0; mt < 4; mt++) {
        #pragma unroll
        for (int nt = 0; nt < 4; nt++) {
            float* p0 = g_P + (size_t)(b * HW + mblk * 128 + rA + mt * 16) * 768 + colb + nt * 8;
            *(float2*)p0 = make_float2(d[mt][nt][0], d[mt][nt][1]);
            *(float2*)(p0 + 8 * 768) = make_float2(d[mt][nt][2], d[mt][nt][3]);
        }
    }
    (void)dummy;
}

// ======================= attention epilogue (unchanged, passing) =======================

static __device__ __forceinline__ void ld8(float* r, const float* p) {
    float4 v0 = *(const float4*)p;
    float4 v1 = *(const float4*)(p + 4);
    r[0] = v0.x; r[1] = v0.y; r[2] = v0.z; r[3] = v0.w;
    r[4] = v1.x; r[5] = v1.y; r[6] = v1.z; r[7] = v1.w;
}

__global__ void __launch_bounds__(256) attn_epilogue_kernel(
    const float* __restrict__ offset, const float* __restrict__ bq,
    float* __restrict__ out) {
    __shared__ float s_kpe[4][256];
    __shared__ float s_vpe[4][256];
    __shared__ float s_out[256 * 33];

    int tid = threadIdx.x;
    int b = blockIdx.z, ty = blockIdx.y, tx0 = blockIdx.x * 32;

    for (int i = tid; i < 1024; i += 256) {
        ((float*)s_kpe)[i] = g_kpe[i];
        ((float*)s_vpe)[i] = g_vpe[i];
    }
    __syncthreads();

    int w = tid >> 5, l = tid & 31;
    int c0 = l * 8;
    const float scale = 0.17677669529663687f;   // 32^-0.5

    float qb[8];
    ld8(qb, bq + c0);

    for (int it = 0; it < 4; it++) {
        int px = w * 4 + it;
        int tx = tx0 + px;
        const float* offp = offset + (((size_t)(b * 256 + ty) * 256 + tx) * 2);
        float fx = (float)tx + offp[0];
        float fy = (float)ty + offp[1];
        float flY = floorf(fy), flX = floorf(fx);
        float dy = fy - flY, dx = fx - flX;
        int iy = (int)flY, ix = (int)flX;

        size_t rb[4];
        #pragma unroll
        for (int uv = 0; uv < 4; uv++) {
            int hh = iy + (uv >> 1); hh = min(max(hh, 0), 255);
            int ww = ix + (uv & 1);  ww = min(max(ww, 0), 255);
            rb[uv] = ((size_t)b * HW + (size_t)(hh * 256 + ww)) * 768;
        }

        float uy = dy * (float)TABN; int gy = (int)uy; float ry = uy - (float)gy;
        float ux = dx * (float)TABN; int gx = (int)ux; float rx = ux - (float)gx;
        float q[8], tA[8], tB[8], tC[8], tD[8];
        ld8(tA, g_qpeY + gy * 256 + c0);
        ld8(tB, g_qpeY + (gy + 1) * 256 + c0);
        ld8(tC, g_qpeX + gx * 256 + c0);
        ld8(tD, g_qpeX + (gx + 1) * 256 + c0);
        #pragma unroll
        for (int j = 0; j < 8; j++)
            q[j] = qb[j] + tA[j] + ry * (tB[j] - tA[j]) + tC[j] + rx * (tD[j] - tC[j]);
        #pragma unroll
        for (int uv = 0; uv < 4; uv++) {
            float f[8];
            ld8(f, g_P + rb[uv] + c0);
            #pragma unroll
            for (int j = 0; j < 8; j++) q[j] = fmaf(0.25f, f[j], q[j]);
        }
        #pragma unroll
        for (int j = 0; j < 8; j++) q[j] *= scale;

        float lg[4];
        #pragma unroll
        for (int uv = 0; uv < 4; uv++) {
            float f[8], p[8];
            ld8(f, g_P + rb[uv] + 256 + c0);
            ld8(p, &s_kpe[uv][c0]);
            float s = 0.f;
            #pragma unroll
            for (int j = 0; j < 8; j++) s = fmaf(q[j], f[j] + p[j], s);
            lg[uv] = s;
        }
        #pragma unroll
        for (int uv = 0; uv < 4; uv++) lg[uv] += __shfl_xor_sync(0xffffffffu, lg[uv], 1);
        #pragma unroll
        for (int uv = 0; uv < 4; uv++) lg[uv] += __shfl_xor_sync(0xffffffffu, lg[uv], 2);

        float mx = fmaxf(fmaxf(lg[0], lg[1]), fmaxf(lg[2], lg[3]));
        float e0 = __expf(lg[0] - mx), e1 = __expf(lg[1] - mx);
        float e2 = __expf(lg[2] - mx), e3 = __expf(lg[3] - mx);
        float inv = 1.0f / (e0 + e1 + e2 + e3);
        float at[4] = {e0 * inv, e1 * inv, e2 * inv, e3 * inv};

        float o[8];
        #pragma unroll
        for (int j = 0; j < 8; j++) o[j] = 0.f;
        #pragma unroll
        for (int uv = 0; uv < 4; uv++) {
            float f[8], p[8];
            ld8(f, g_P + rb[uv] + 512 + c0);
            ld8(p, &s_vpe[uv][c0]);
            #pragma unroll
            for (int j = 0; j < 8; j++) o[j] = fmaf(at[uv], f[j] + p[j], o[j]);
        }
        #pragma unroll
        for (int j = 0; j < 8; j++) s_out[(c0 + j) * 33 + px] = o[j];
    }
    __syncthreads();

    for (int idx = tid; idx < 256 * 32; idx += 256) {
        int c = idx >> 5, px = idx & 31;
        out[((size_t)(b * 256 + c) * 256 + ty) * 256 + tx0 + px] = s_out[c * 33 + px];
    }
}

// ======================= launch =======================

extern "C" void kernel_launch(void* const* d_in, const int* in_sizes, int n_in,
                              void* d_out, int out_size) {
    (void)in_sizes; (void)n_in; (void)out_size;
    const float* feat   = (const float*)d_in[0];
    const float* offset = (const float*)d_in[1];
    const float* Wq     = (const float*)d_in[2];
    const float* bq     = (const float*)d_in[3];
    const float* Wk     = (const float*)d_in[4];
    const float* bk     = (const float*)d_in[5];
    const float* Wv     = (const float*)d_in[6];
    const float* bv     = (const float*)d_in[7];
    float* out = (float*)d_out;

    static int attr_set = 0;
    if (!attr_set) {
        cudaFuncSetAttribute(proj_mma2_kernel,
                             cudaFuncAttributeMaxDynamicSharedMemorySize, SMEM_MMA);
        attr_set = 1;
    }

    prestage_w_kernel<<<dim3(6, 8), 256>>>(Wq, Wk, Wv);
    prestage_feat_kernel<<<dim3(512, 8, B_), 256>>>(feat);
    build_kvpe_kernel<<<4, 256>>>(Wk, bk, Wv, bv);
    qpetab_gemm_kernel<<<dim3((TABN + 32) / 32, 4), 256>>>(Wq);
    proj_mma2_kernel<<<dim3(6, 512, B_), 256, SMEM_MMA>>>(0);
    attn_epilogue_kernel<<<dim3(8, 256, B_), 256>>>(offset, bq, out);
}